// round 16
// baseline (speedup 1.0000x reference)
#include <cuda_runtime.h>
#include <cuda_fp16.h>
#include <cstdint>

// ---------------- problem constants ----------------
#define GRID     128
#define NTHREADS 512
#define SQ       2048
#define H        512
#define HBH      16384     // elements per (t, half) plane: 512 units x 32 batches
#define GPLD     34

// smem byte offsets
#define SMEM_SB   0        // 3 staging buffers x 16KB (h fp16), K=256 chunks
#define SMEM_W1   49152    // layer1 Whh fp16: 32KB
#define SMEM_W2   81920    // layer2 (Wih2|Whh2) fp16: 64KB
#define SMEM_GPA  147456   // 2 x 32 x GPLD x f32 (layer1 gates, per K-half)
#define SMEM_GPB  156160   // 2 x 32 x GPLD x f32 (layer2 gates, per K-half)
#define SMEM_E2S  164864   // 16 pairs x 32 rows f32
#define SMEM_BS   166912   // 64 f32 (L1 bias | L2 bias)
#define SMEM_TOT  167168

// ---------------- device scratch ----------------
__device__ __align__(16) __half g_h1h[(SQ + 1) * 2 * HBH];
__device__ __align__(16) __half g_h2h[2 * 2 * HBH];
__device__ __align__(16) float g_E2[16 * 4 * H];
__device__ int      g_pidx[SQ * 64];
__device__ unsigned g_isI32;
// split arrive/wait barrier trees (A: h1 ready at mid-interval, B: h2 ready at end)
__device__ unsigned g_cA1[2 * 8 * 32], g_cA2[2 * 32], g_genA[2 * 32];
__device__ unsigned g_cB1[2 * 8 * 32], g_cB2[2 * 32], g_genB[2 * 32];

// element offset inside one (t, half) plane: paired-k 128B rows, XOR swizzle
__device__ __forceinline__ int eoff_h(int k, int b) {
    return (k >> 1) * 64 + (k & 1) * 32 + ((((b >> 3) ^ ((k >> 1) & 3))) << 3) + (b & 7);
}

// ---------------- PTX helpers ----------------
__device__ __forceinline__ float tanh_ap(float x) {
    float y;
    asm("tanh.approx.f32 %0,%1;" : "=f"(y) : "f"(x));
    return y;
}
__device__ __forceinline__ float sig_ap(float x) {
    return fmaf(0.5f, tanh_ap(0.5f * x), 0.5f);
}
__device__ __forceinline__ void ldmx4t(unsigned* r, uint32_t a) {
    asm volatile("ldmatrix.sync.aligned.m8n8.x4.trans.shared.b16 {%0,%1,%2,%3},[%4];"
                 : "=r"(r[0]), "=r"(r[1]), "=r"(r[2]), "=r"(r[3]) : "r"(a));
}
__device__ __forceinline__ void ldmx2t(unsigned* r, uint32_t a) {
    asm volatile("ldmatrix.sync.aligned.m8n8.x2.trans.shared.b16 {%0,%1},[%2];"
                 : "=r"(r[0]), "=r"(r[1]) : "r"(a));
}
__device__ __forceinline__ void mma16816(float* d, const unsigned* a, const unsigned* b) {
    asm volatile("mma.sync.aligned.m16n8k16.row.col.f32.f16.f16.f32 "
                 "{%0,%1,%2,%3},{%4,%5,%6,%7},{%8,%9},{%0,%1,%2,%3};"
                 : "+f"(d[0]), "+f"(d[1]), "+f"(d[2]), "+f"(d[3])
                 : "r"(a[0]), "r"(a[1]), "r"(a[2]), "r"(a[3]), "r"(b[0]), "r"(b[1]));
}
__device__ __forceinline__ void stg_h16(__half* p, __half v) {
    unsigned short u = *reinterpret_cast<unsigned short*>(&v);
    asm volatile("st.global.cg.u16 [%0], %1;" :: "l"(p), "h"(u) : "memory");
}
__device__ __forceinline__ float ldg_h16(const __half* p) {
    unsigned short u;
    asm volatile("ld.global.cg.u16 %0,[%1];" : "=h"(u) : "l"(p));
    __half b = *reinterpret_cast<__half*>(&u);
    return __half2float(b);
}
__device__ __forceinline__ unsigned acq_load(const unsigned* p) {
    unsigned v;
    asm volatile("ld.acquire.gpu.global.u32 %0,[%1];" : "=r"(v) : "l"(p) : "memory");
    return v;
}

// hierarchical arrive: 8 groups of 8, root of 8, post gen=val on completion.
// Counters self-reset; a CTA's next-round arrival provably follows the post
// (it passes the matching wait first).
__device__ __forceinline__ void arrive_tree(unsigned* c1, unsigned* c2,
                                            unsigned* gen, unsigned val) {
    unsigned p1;
    asm volatile("atom.acq_rel.gpu.global.add.u32 %0,[%1],%2;"
                 : "=r"(p1) : "l"(c1), "r"(1u) : "memory");
    if (p1 == 7u) {
        asm volatile("st.relaxed.gpu.global.u32 [%0],%1;" :: "l"(c1), "r"(0u) : "memory");
        unsigned p2;
        asm volatile("atom.acq_rel.gpu.global.add.u32 %0,[%1],%2;"
                     : "=r"(p2) : "l"(c2), "r"(1u) : "memory");
        if (p2 == 7u) {
            asm volatile("st.relaxed.gpu.global.u32 [%0],%1;" :: "l"(c2), "r"(0u) : "memory");
            asm volatile("st.release.gpu.global.u32 [%0],%1;" :: "l"(gen), "r"(val) : "memory");
        }
    }
}
__device__ __forceinline__ void wait_gen(const unsigned* gen, unsigned target) {
    unsigned cur;
    do { cur = acq_load(gen); } while ((int)(cur - target) < 0);
}

// stage one 16KB chunk (K=256 of h fp16); 2 cp.async per thread (512 threads)
__device__ __forceinline__ void stage16(uint32_t sb, const __half* gh, int tid) {
    uint32_t s = sb + (uint32_t)tid * 16u;
    asm volatile("cp.async.cg.shared.global [%0],[%1],16;"
                 :: "r"(s), "l"((const char*)gh + tid * 16) : "memory");
    asm volatile("cp.async.cg.shared.global [%0],[%1],16;"
                 :: "r"(s + 8192u), "l"((const char*)gh + 8192 + tid * 16) : "memory");
}
#define CP_COMMIT() asm volatile("cp.async.commit_group;" ::: "memory")
#define CP_WAIT1()  asm volatile("cp.async.wait_group 1;" ::: "memory")
#define CP_WAIT0()  asm volatile("cp.async.wait_group 0;" ::: "memory")

// ---------------- setup kernels ----------------
__global__ void detect_reset() { g_isI32 = 0u; }

// int64 values in [0,4) -> odd u32 words all zero; int32 -> some nonzero.
__global__ void detect_dtype(const unsigned* __restrict__ w) {
    int i = blockIdx.x * blockDim.x + threadIdx.x;
    if (i < SQ * 64) {
        if ((i & 1) && w[i] != 0u) atomicOr(&g_isI32, 1u);
    }
}

__global__ void setup_misc(const void* __restrict__ inp_raw) {
    int i = blockIdx.x * blockDim.x + threadIdx.x;
    if (i < SQ * 64) {
        int s = i >> 6, b = i & 63;
        long long a, c;
        if (g_isI32) {
            const int* p = (const int*)inp_raw;
            a = p[b * SQ + s];
            c = p[(64 + b) * SQ + s];
        } else {
            const long long* p = (const long long*)inp_raw;
            a = p[(long long)b * SQ + s];
            c = p[(long long)(64 + b) * SQ + s];
        }
        g_pidx[s * 64 + b] = (int)(a * 4 + c);
    }
    __half z = __float2half(0.f);
    if (i < 2 * HBH) g_h1h[i] = z;
    if (i < 4 * HBH) g_h2h[i] = z;
}

__global__ void setup_e2(const float* __restrict__ embed, const float* __restrict__ Wih) {
    int flat = blockIdx.x * blockDim.x + threadIdx.x;
    int p = flat >> 11, r = flat & 2047;
    const float* e0 = embed + (p >> 2) * H;
    const float* e1 = embed + (p & 3) * H;
    const float* w  = Wih + (size_t)r * H;
    float s = 0.f;
    #pragma unroll 4
    for (int k = 0; k < H; k++) s += (e0[k] + e1[k]) * w[k];
    g_E2[p * 2048 + r] = s;
}

// ---------------- persistent merged-layer LSTM kernel ----------------
// Interval i: layer1[t=i] (i<SQ) and layer2[t=i-1] (i>0). Split barriers:
// arrive-A (h1[i+1] ready) mid-interval; arrive-B (h2 parity ready) at end.
// wait-A gates interval start (h1 staging); wait-B gates h2 staging (phase 0 end).
__global__ __launch_bounds__(NTHREADS, 1)
void lstm_persist(const float* __restrict__ Wih, const float* __restrict__ Whh,
                  const float* __restrict__ bih, const float* __restrict__ bhh,
                  const float* __restrict__ ln_g, const float* __restrict__ ln_b,
                  const float* __restrict__ Wp,  const float* __restrict__ bp,
                  float* __restrict__ out)
{
    extern __shared__ char smem[];
    __half* w1h = (__half*)(smem + SMEM_W1);
    __half* w2h = (__half*)(smem + SMEM_W2);
    float* gpA = (float*)(smem + SMEM_GPA);     // [2][32][GPLD]
    float* gpB = (float*)(smem + SMEM_GPB);     // [2][32][GPLD]
    float* E2s = (float*)(smem + SMEM_E2S);
    float* bs  = (float*)(smem + SMEM_BS);
    uint32_t su = (uint32_t)__cvta_generic_to_shared(smem);
    const uint32_t SBu = su + SMEM_SB, W1u = su + SMEM_W1, W2u = su + SMEM_W2;
    __shared__ unsigned s_bA, s_bB;

    const int cta  = blockIdx.x;
    const int tid  = threadIdx.x;
    const int warp = tid >> 5, lane = tid & 31;
    const int ug   = cta >> 1;
    const int bh   = cta & 1;
    const int grp  = ug >> 3;
    const int ks = warp >> 3;          // K-half 0..1
    const int rn = (warp >> 1) & 3;    // row n8-tile 0..3
    const int bm = warp & 1;           // batch m16-tile 0..1
    const int uu = tid >> 5, bl_e = tid & 31;   // eltwise map (tid<256)

    unsigned* cA1 = g_cA1 + (bh * 8 + grp) * 32;
    unsigned* cA2 = g_cA2 + bh * 32;
    unsigned* gA  = g_genA + bh * 32;
    unsigned* cB1 = g_cB1 + (bh * 8 + grp) * 32;
    unsigned* cB2 = g_cB2 + bh * 32;
    unsigned* gB  = g_genB + bh * 32;

    // ldmatrix per-lane offsets (proven R6..R15 formulas)
    const int kA  = (lane & 7) + ((lane & 16) >> 1);
    const int jbA = bm * 2 + ((lane >> 3) & 1);
    const uint32_t aoff = (uint32_t)((kA >> 1) * 128 + (kA & 1) * 64 +
                                     ((jbA ^ ((kA >> 1) & 3)) << 4));
    const int kB  = lane & 15;
    const uint32_t bOff = (uint32_t)((kB >> 1) * 128 + (kB & 1) * 64 +
                                     ((rn ^ ((kB >> 1) & 3)) << 4));
    const int dr = rn * 8 + ((lane & 3) << 1);
    const int dc = bm * 16 + (lane >> 2);
    float* gpA_w = gpA + ks * 32 * GPLD;
    float* gpB_w = gpB + ks * 32 * GPLD;

    if (tid == 0) {
        unsigned a_, b_;
        asm volatile("ld.relaxed.gpu.global.u32 %0,[%1];" : "=r"(a_) : "l"(gA) : "memory");
        asm volatile("ld.relaxed.gpu.global.u32 %0,[%1];" : "=r"(b_) : "l"(gB) : "memory");
        s_bA = a_; s_bB = b_;
    }
    __syncthreads();
    const unsigned bA = s_bA, bB = s_bB;

    // ======== weight conversion (fp16): W1 (Whh l0), W2 (Wih1|Whh1) ========
    for (int idx = tid; idx < 32 * H; idx += NTHREADS) {
        int r = idx >> 9, k = idx & (H - 1);
        int R = ((r >> 3) << 9) + (ug << 3) + (r & 7);
        float w = Whh[(size_t)R * H + k];
        int e = (k >> 1) * 64 + (k & 1) * 32 + ((((r >> 3) ^ ((k >> 1) & 3))) << 3) + (r & 7);
        w1h[e] = __float2half(w);
    }
    {
        const float* Wih1 = Wih + (size_t)4 * H * H;
        const float* Whh1 = Whh + (size_t)4 * H * H;
        for (int idx = tid; idx < 32 * 2 * H; idx += NTHREADS) {
            int r = idx >> 10, k = idx & 1023;
            int R = ((r >> 3) << 9) + (ug << 3) + (r & 7);
            float w = (k < H) ? Wih1[(size_t)R * H + k] : Whh1[(size_t)R * H + (k - H)];
            int e = (k >> 1) * 64 + (k & 1) * 32 + ((((r >> 3) ^ ((k >> 1) & 3))) << 3) + (r & 7);
            w2h[e] = __float2half(w);
        }
    }
    for (int idx = tid; idx < 512; idx += NTHREADS) {
        int p = idx >> 5, r = idx & 31;
        int R = ((r >> 3) << 9) + (ug << 3) + (r & 7);
        E2s[idx] = g_E2[p * 2048 + R];
    }
    if (tid < 32) {
        int R = ((tid >> 3) << 9) + (ug << 3) + (tid & 7);
        bs[tid]      = bih[R] + bhh[R];
        bs[tid + 32] = bih[2048 + R] + bhh[2048 + R];
    }
    __syncthreads();

    float cst1 = 0.f, cst2 = 0.f;

    for (int i = 0; i <= SQ; ++i) {
        const bool doL1 = (i < SQ);
        const bool doL2 = (i > 0);
        const int  nch  = doL2 ? 4 : 2;            // K=256 chunks: 2 h1 + 2 h2
        const size_t base1 = (size_t)(i * 2 + bh) * HBH;
        const size_t base2 = (size_t)((((i - 1) & 1)) * 2 + bh) * HBH;

        // wait-A: h1 slot i complete (posted at mid of interval i-1)
        if (tid == 0 && i > 0) wait_gen(gA, bA + (unsigned)i);
        __syncthreads();

        // prologue: stage h1 chunks 0,1
        stage16(SBu + 0u,     g_h1h + base1, tid);        CP_COMMIT();
        stage16(SBu + 16384u, g_h1h + base1 + 8192, tid); CP_COMMIT();

        float d1[4] = {0,0,0,0}, d2[4] = {0,0,0,0};

        for (int c = 0; c < nch; ++c) {
            if (c < nch - 1) { CP_WAIT1(); } else { CP_WAIT0(); }
            __syncthreads();                       // chunk c visible; buf (c-1) free

            if (c == 1 && nch == 4) {              // stage h2 chunk 3 (B passed at c==0)
                stage16(SBu + (uint32_t)(3 % 3) * 16384u, g_h2h + base2 + 8192, tid);
                CP_COMMIT();
            }

            // MMA on chunk c
            {
                uint32_t ab = SBu + (uint32_t)(c % 3) * 16384u + (uint32_t)ks * 8192u + aoff;
                uint32_t b1 = W1u + (uint32_t)c * 16384u + (uint32_t)ks * 8192u + bOff;
                uint32_t b2 = W2u + (uint32_t)c * 16384u + (uint32_t)ks * 8192u + bOff;
                const bool l1 = (c < 2) && doL1;
                #pragma unroll
                for (int t = 0; t < 8; ++t) {
                    unsigned Ah[4], Bh_[2];
                    ldmx4t(Ah, ab);
                    if (l1) {
                        ldmx2t(Bh_, b1);
                        mma16816(d1, Ah, Bh_);
                    }
                    if (doL2) {
                        ldmx2t(Bh_, b2);
                        mma16816(d2, Ah, Bh_);
                    }
                    ab += 1024u; b1 += 1024u; b2 += 1024u;
                }
            }

            if (c == 0) {
                // wait-B: h2 parity (i-1)&1 complete (posted end of interval i-1)
                if (tid == 0 && i > 0) wait_gen(gB, bB + (unsigned)i);
                __syncthreads();
                if (nch == 4) {                     // stage h2 chunk 2
                    stage16(SBu + (uint32_t)(2 % 3) * 16384u, g_h2h + base2, tid);
                    CP_COMMIT();
                }
            }

            if (c == 1) {
                // ---- mid-interval: L1 eltwise + h1 store + arrive-A ----
                if (doL1) {
                    gpA_w[dr * GPLD + dc]           = d1[0];
                    gpA_w[(dr + 1) * GPLD + dc]     = d1[1];
                    gpA_w[dr * GPLD + dc + 8]       = d1[2];
                    gpA_w[(dr + 1) * GPLD + dc + 8] = d1[3];
                }
                __syncthreads();
                if (doL1 && tid < 256) {
                    int p = g_pidx[i * 64 + bh * 32 + bl_e];
                    float gv[4];
                    #pragma unroll
                    for (int gate = 0; gate < 4; ++gate) {
                        int r = (gate << 3) + uu;
                        gv[gate] = bs[r] + E2s[(p << 5) + r]
                                 + gpA[r * GPLD + bl_e] + gpA[(32 + r) * GPLD + bl_e];
                    }
                    float ig = sig_ap(gv[0]);
                    float fg = sig_ap(gv[1]);
                    float gg = tanh_ap(gv[2]);
                    float og = sig_ap(gv[3]);
                    cst1 = fg * cst1 + ig * gg;
                    float hv = og * tanh_ap(cst1);
                    size_t off = (size_t)((i + 1) * 2 + bh) * HBH + eoff_h((ug << 3) + uu, bl_e);
                    stg_h16(g_h1h + off, __float2half(hv));
                }
                __syncthreads();
                if (tid == 0) arrive_tree(cA1, cA2, gA, bA + (unsigned)(i + 1));
            }
        }

        // ---- end: L2 eltwise + h2 store + arrive-B ----
        if (doL2) {
            gpB_w[dr * GPLD + dc]           = d2[0];
            gpB_w[(dr + 1) * GPLD + dc]     = d2[1];
            gpB_w[dr * GPLD + dc + 8]       = d2[2];
            gpB_w[(dr + 1) * GPLD + dc + 8] = d2[3];
        }
        __syncthreads();
        if (doL2 && tid < 256) {
            float gv[4];
            #pragma unroll
            for (int gate = 0; gate < 4; ++gate) {
                int r = (gate << 3) + uu;
                gv[gate] = bs[32 + r]
                         + gpB[r * GPLD + bl_e] + gpB[(32 + r) * GPLD + bl_e];
            }
            float ig = sig_ap(gv[0]);
            float fg = sig_ap(gv[1]);
            float gg = tanh_ap(gv[2]);
            float og = sig_ap(gv[3]);
            cst2 = fg * cst2 + ig * gg;
            float hv = og * tanh_ap(cst2);
            size_t off = (size_t)((i & 1) * 2 + bh) * HBH + eoff_h((ug << 3) + uu, bl_e);
            stg_h16(g_h2h + off, __float2half(hv));
        }
        __syncthreads();
        if (tid == 0) arrive_tree(cB1, cB2, gB, bB + (unsigned)(i + 1));
    }

    // ======== head: LayerNorm + projection (final h2 at parity 0) ========
    if (cta < 8) {
        if (tid == 0) wait_gen(gB, bB + (unsigned)(SQ + 1));
        __syncthreads();
        if (warp < 8) {
            int half = cta & 1;
            int bl = ((cta >> 1) << 3) + warp;
            const __half* h2h = g_h2h + (size_t)half * HBH;
            float s1 = 0.f, s2 = 0.f;
            for (int u = lane; u < H; u += 32) {
                float v = ldg_h16(h2h + eoff_h(u, bl));
                s1 += v; s2 += v * v;
            }
            #pragma unroll
            for (int o = 16; o; o >>= 1) {
                s1 += __shfl_xor_sync(0xFFFFFFFFu, s1, o);
                s2 += __shfl_xor_sync(0xFFFFFFFFu, s2, o);
            }
            float mu  = s1 * (1.f / H);
            float var = s2 * (1.f / H) - mu * mu;
            float rs  = rsqrtf(var + 1e-5f);
            float acc = 0.f;
            for (int u = lane; u < H; u += 32) {
                float v  = ldg_h16(h2h + eoff_h(u, bl));
                float hn = (v - mu) * rs * ln_g[u] + ln_b[u];
                acc += hn * Wp[u];
            }
            #pragma unroll
            for (int o = 16; o; o >>= 1) acc += __shfl_xor_sync(0xFFFFFFFFu, acc, o);
            if (lane == 0) out[half * 32 + bl] = acc + bp[0];
        }
    }
}

// ---------------- launch ----------------
extern "C" void kernel_launch(void* const* d_in, const int* in_sizes, int n_in,
                              void* d_out, int out_size) {
    const void*  inp   = d_in[0];
    const float* embed = (const float*)d_in[1];
    const float* Wih   = (const float*)d_in[2];
    const float* Whh   = (const float*)d_in[3];
    const float* bih   = (const float*)d_in[4];
    const float* bhh   = (const float*)d_in[5];
    const float* ln_g  = (const float*)d_in[6];
    const float* ln_b  = (const float*)d_in[7];
    const float* Wp    = (const float*)d_in[8];
    const float* bp    = (const float*)d_in[9];
    float* out = (float*)d_out;

    detect_reset<<<1, 1>>>();
    detect_dtype<<<512, 256>>>((const unsigned*)inp);
    setup_misc<<<512, 256>>>(inp);
    setup_e2<<<128, 256>>>(embed, Wih);

    cudaFuncSetAttribute(lstm_persist, cudaFuncAttributeMaxDynamicSharedMemorySize, SMEM_TOT);
    lstm_persist<<<GRID, NTHREADS, SMEM_TOT>>>(Wih, Whh, bih, bhh, ln_g, ln_b, Wp, bp, out);
}

// round 17
// speedup vs baseline: 1.3448x; 1.3448x over previous
#include <cuda_runtime.h>
#include <cuda_fp16.h>
#include <cstdint>

// ---------------- problem constants ----------------
#define GRID     128
#define NTHREADS 512
#define SQ       2048
#define H        512
#define HBH      16384     // elements per (t, half) plane: 512 units x 32 batches
#define GPLD     34

// smem byte offsets
#define SMEM_SB   0        // 3 staging buffers x 16KB (h fp16), K=256 chunks
#define SMEM_W1   49152    // layer1 Whh fp16: 32KB
#define SMEM_W2   81920    // layer2 (Wih2|Whh2) fp16: 64KB
#define SMEM_GPA  147456   // 2 x 32 x GPLD x f32 (layer1 gates, per K-half)
#define SMEM_GPB  156160   // 2 x 32 x GPLD x f32 (layer2 gates, per K-half)
#define SMEM_E2S  164864   // 16 pairs x 32 rows f32
#define SMEM_BS   166912   // 64 f32 (L1 bias | L2 bias)
#define SMEM_TOT  167168

// ---------------- device scratch ----------------
__device__ __align__(16) __half g_h1h[(SQ + 1) * 2 * HBH];
__device__ __align__(16) __half g_h2h[2 * 2 * HBH];
__device__ __align__(16) float g_E2[16 * 4 * H];
__device__ int      g_pidx[SQ * 64];
__device__ unsigned g_isI32;
__device__ unsigned g_fl[2 * 64 * 32];   // per-CTA interval flags, 128B apart

__device__ __forceinline__ float tanh_ap(float x) {
    float y;
    asm("tanh.approx.f32 %0,%1;" : "=f"(y) : "f"(x));
    return y;
}
__device__ __forceinline__ float sig_ap(float x) {
    return fmaf(0.5f, tanh_ap(0.5f * x), 0.5f);
}

// element offset inside one (t, half) plane: paired-k 128B rows, XOR swizzle
__device__ __forceinline__ int eoff_h(int k, int b) {
    return (k >> 1) * 64 + (k & 1) * 32 + ((((b >> 3) ^ ((k >> 1) & 3))) << 3) + (b & 7);
}

// ---------------- PTX helpers ----------------
__device__ __forceinline__ void ldmx4t(unsigned* r, uint32_t a) {
    asm volatile("ldmatrix.sync.aligned.m8n8.x4.trans.shared.b16 {%0,%1,%2,%3},[%4];"
                 : "=r"(r[0]), "=r"(r[1]), "=r"(r[2]), "=r"(r[3]) : "r"(a));
}
__device__ __forceinline__ void ldmx2t(unsigned* r, uint32_t a) {
    asm volatile("ldmatrix.sync.aligned.m8n8.x2.trans.shared.b16 {%0,%1},[%2];"
                 : "=r"(r[0]), "=r"(r[1]) : "r"(a));
}
__device__ __forceinline__ void mma16816(float* d, const unsigned* a, const unsigned* b) {
    asm volatile("mma.sync.aligned.m16n8k16.row.col.f32.f16.f16.f32 "
                 "{%0,%1,%2,%3},{%4,%5,%6,%7},{%8,%9},{%0,%1,%2,%3};"
                 : "+f"(d[0]), "+f"(d[1]), "+f"(d[2]), "+f"(d[3])
                 : "r"(a[0]), "r"(a[1]), "r"(a[2]), "r"(a[3]), "r"(b[0]), "r"(b[1]));
}
__device__ __forceinline__ void stg_h16(__half* p, __half v) {
    unsigned short u = *reinterpret_cast<unsigned short*>(&v);
    asm volatile("st.global.cg.u16 [%0], %1;" :: "l"(p), "h"(u) : "memory");
}
__device__ __forceinline__ float ldg_h16(const __half* p) {
    unsigned short u;
    asm volatile("ld.global.cg.u16 %0,[%1];" : "=h"(u) : "l"(p));
    __half b = *reinterpret_cast<__half*>(&u);
    return __half2float(b);
}
__device__ __forceinline__ unsigned acq_load(const unsigned* p) {
    unsigned v;
    asm volatile("ld.acquire.gpu.global.u32 %0,[%1];" : "=r"(v) : "l"(p) : "memory");
    return v;
}

// Flat broadcast barrier: tid0 release-stores own flag; 64 threads poll the 64
// per-CTA flags in parallel (one L2 RT when already satisfied). No atomics.
// Monotonic targets; replay-safe via base snapshot of own flag.
__device__ __forceinline__ void flag_barrier(unsigned target, int bh, int ug, int tid) {
    __syncthreads();
    if (tid == 0)
        asm volatile("st.release.gpu.global.u32 [%0],%1;"
                     :: "l"(&g_fl[(bh * 64 + ug) * 32]), "r"(target) : "memory");
    if (tid < 64) {
        const unsigned* f = &g_fl[(bh * 64 + tid) * 32];
        while ((int)(acq_load(f) - target) < 0) { }
    }
    __syncthreads();
}

// stage one 16KB chunk (K=256 of h fp16); 2 cp.async per thread (512 threads)
__device__ __forceinline__ void stage16(uint32_t sb, const __half* gh, int tid) {
    uint32_t s = sb + (uint32_t)tid * 16u;
    asm volatile("cp.async.cg.shared.global [%0],[%1],16;"
                 :: "r"(s), "l"((const char*)gh + tid * 16) : "memory");
    asm volatile("cp.async.cg.shared.global [%0],[%1],16;"
                 :: "r"(s + 8192u), "l"((const char*)gh + 8192 + tid * 16) : "memory");
}
#define CP_COMMIT() asm volatile("cp.async.commit_group;" ::: "memory")
#define CP_WAIT1()  asm volatile("cp.async.wait_group 1;" ::: "memory")
#define CP_WAIT0()  asm volatile("cp.async.wait_group 0;" ::: "memory")

// ---------------- setup kernels ----------------
__global__ void detect_reset() { g_isI32 = 0u; }

// int64 values in [0,4) -> odd u32 words all zero; int32 -> some nonzero.
__global__ void detect_dtype(const unsigned* __restrict__ w) {
    int i = blockIdx.x * blockDim.x + threadIdx.x;
    if (i < SQ * 64) {
        if ((i & 1) && w[i] != 0u) atomicOr(&g_isI32, 1u);
    }
}

__global__ void setup_misc(const void* __restrict__ inp_raw) {
    int i = blockIdx.x * blockDim.x + threadIdx.x;
    if (i < SQ * 64) {
        int s = i >> 6, b = i & 63;
        long long a, c;
        if (g_isI32) {
            const int* p = (const int*)inp_raw;
            a = p[b * SQ + s];
            c = p[(64 + b) * SQ + s];
        } else {
            const long long* p = (const long long*)inp_raw;
            a = p[(long long)b * SQ + s];
            c = p[(long long)(64 + b) * SQ + s];
        }
        g_pidx[s * 64 + b] = (int)(a * 4 + c);
    }
    __half z = __float2half(0.f);
    if (i < 2 * HBH) g_h1h[i] = z;
    if (i < 4 * HBH) g_h2h[i] = z;
}

__global__ void setup_e2(const float* __restrict__ embed, const float* __restrict__ Wih) {
    int flat = blockIdx.x * blockDim.x + threadIdx.x;
    int p = flat >> 11, r = flat & 2047;
    const float* e0 = embed + (p >> 2) * H;
    const float* e1 = embed + (p & 3) * H;
    const float* w  = Wih + (size_t)r * H;
    float s = 0.f;
    #pragma unroll 4
    for (int k = 0; k < H; k++) s += (e0[k] + e1[k]) * w[k];
    g_E2[p * 2048 + r] = s;
}

// ---------------- persistent merged-layer LSTM kernel ----------------
// CTA = (ug = cta>>1 unit-group 0..63, bh = cta&1 batch half). Interval i:
// layer1[t=i] (i<SQ) and layer2[t=i-1] (i>0), sharing staged h1 slot-i chunks.
// 4 K=256 phases per interval; 16 warps = (ks x rn x bm), K split across ks.
// One flat broadcast barrier per interval.
__global__ __launch_bounds__(NTHREADS, 1)
void lstm_persist(const float* __restrict__ Wih, const float* __restrict__ Whh,
                  const float* __restrict__ bih, const float* __restrict__ bhh,
                  const float* __restrict__ ln_g, const float* __restrict__ ln_b,
                  const float* __restrict__ Wp,  const float* __restrict__ bp,
                  float* __restrict__ out)
{
    extern __shared__ char smem[];
    __half* w1h = (__half*)(smem + SMEM_W1);
    __half* w2h = (__half*)(smem + SMEM_W2);
    float* gpA = (float*)(smem + SMEM_GPA);     // [2][32][GPLD]
    float* gpB = (float*)(smem + SMEM_GPB);     // [2][32][GPLD]
    float* E2s = (float*)(smem + SMEM_E2S);
    float* bs  = (float*)(smem + SMEM_BS);
    uint32_t su = (uint32_t)__cvta_generic_to_shared(smem);
    const uint32_t SBu = su + SMEM_SB, W1u = su + SMEM_W1, W2u = su + SMEM_W2;
    __shared__ unsigned s_base;

    const int cta  = blockIdx.x;
    const int tid  = threadIdx.x;
    const int warp = tid >> 5, lane = tid & 31;
    const int ug   = cta >> 1;
    const int bh   = cta & 1;
    const int ks = warp >> 3;          // K-half 0..1
    const int rn = (warp >> 1) & 3;    // row n8-tile 0..3
    const int bm = warp & 1;           // batch m16-tile 0..1
    const int uu = tid >> 5, bl_e = tid & 31;   // eltwise map (tid<256)

    // ldmatrix per-lane offsets (proven R6..R15 formulas)
    const int kA  = (lane & 7) + ((lane & 16) >> 1);
    const int jbA = bm * 2 + ((lane >> 3) & 1);
    const uint32_t aoff = (uint32_t)((kA >> 1) * 128 + (kA & 1) * 64 +
                                     ((jbA ^ ((kA >> 1) & 3)) << 4));
    const int kB  = lane & 15;
    const uint32_t bOff = (uint32_t)((kB >> 1) * 128 + (kB & 1) * 64 +
                                     ((rn ^ ((kB >> 1) & 3)) << 4));
    const int dr = rn * 8 + ((lane & 3) << 1);
    const int dc = bm * 16 + (lane >> 2);
    float* gpA_w = gpA + ks * 32 * GPLD;
    float* gpB_w = gpB + ks * 32 * GPLD;

    if (tid == 0) {
        unsigned b_;
        asm volatile("ld.relaxed.gpu.global.u32 %0,[%1];"
                     : "=r"(b_) : "l"(&g_fl[(bh * 64 + ug) * 32]) : "memory");
        s_base = b_;
    }
    __syncthreads();
    unsigned gen = s_base;

    // ======== weight conversion (fp16): W1 (Whh l0), W2 (Wih1|Whh1) ========
    for (int idx = tid; idx < 32 * H; idx += NTHREADS) {
        int r = idx >> 9, k = idx & (H - 1);
        int R = ((r >> 3) << 9) + (ug << 3) + (r & 7);
        float w = Whh[(size_t)R * H + k];
        int e = (k >> 1) * 64 + (k & 1) * 32 + ((((r >> 3) ^ ((k >> 1) & 3))) << 3) + (r & 7);
        w1h[e] = __float2half(w);
    }
    {
        const float* Wih1 = Wih + (size_t)4 * H * H;
        const float* Whh1 = Whh + (size_t)4 * H * H;
        for (int idx = tid; idx < 32 * 2 * H; idx += NTHREADS) {
            int r = idx >> 10, k = idx & 1023;
            int R = ((r >> 3) << 9) + (ug << 3) + (r & 7);
            float w = (k < H) ? Wih1[(size_t)R * H + k] : Whh1[(size_t)R * H + (k - H)];
            int e = (k >> 1) * 64 + (k & 1) * 32 + ((((r >> 3) ^ ((k >> 1) & 3))) << 3) + (r & 7);
            w2h[e] = __float2half(w);
        }
    }
    for (int idx = tid; idx < 512; idx += NTHREADS) {
        int p = idx >> 5, r = idx & 31;
        int R = ((r >> 3) << 9) + (ug << 3) + (r & 7);
        E2s[idx] = g_E2[p * 2048 + R];
    }
    if (tid < 32) {
        int R = ((tid >> 3) << 9) + (ug << 3) + (tid & 7);
        bs[tid]      = bih[R] + bhh[R];
        bs[tid + 32] = bih[2048 + R] + bhh[2048 + R];
    }
    __syncthreads();

    float cst1 = 0.f, cst2 = 0.f;

    for (int i = 0; i <= SQ; ++i) {
        const bool doL1 = (i < SQ);
        const bool doL2 = (i > 0);
        const int  nch  = doL2 ? 4 : 2;            // K=256 chunks: 2 h1 + 2 h2
        const size_t base1 = (size_t)(i * 2 + bh) * HBH;
        const size_t base2 = (size_t)((((i - 1) & 1)) * 2 + bh) * HBH;

        // prologue: stage chunks 0,1
        #pragma unroll
        for (int n = 0; n < 2; ++n) {
            const __half* gh = (n < 2) ? (g_h1h + base1 + n * 8192)
                                       : (g_h2h + base2 + (n - 2) * 8192);
            stage16(SBu + n * 16384u, gh, tid);
            CP_COMMIT();
        }

        float d1[4] = {0,0,0,0}, d2[4] = {0,0,0,0};

        for (int c = 0; c < nch; ++c) {
            if (c < nch - 1) { CP_WAIT1(); } else { CP_WAIT0(); }
            __syncthreads();                       // chunk c visible; buf (c-1) free

            int n = c + 2;
            if (n < nch) {
                const __half* gh = (n < 2) ? (g_h1h + base1 + n * 8192)
                                           : (g_h2h + base2 + (n - 2) * 8192);
                stage16(SBu + (uint32_t)(n % 3) * 16384u, gh, tid);
                CP_COMMIT();
            }

            uint32_t ab = SBu + (uint32_t)(c % 3) * 16384u + (uint32_t)ks * 8192u + aoff;
            uint32_t b1 = W1u + (uint32_t)c * 16384u + (uint32_t)ks * 8192u + bOff;
            uint32_t b2 = W2u + (uint32_t)c * 16384u + (uint32_t)ks * 8192u + bOff;
            const bool l1 = (c < 2) && doL1;
            #pragma unroll
            for (int t = 0; t < 8; ++t) {
                unsigned Ah[4], Bh_[2];
                ldmx4t(Ah, ab);
                if (l1) {
                    ldmx2t(Bh_, b1);
                    mma16816(d1, Ah, Bh_);
                }
                if (doL2) {
                    ldmx2t(Bh_, b2);
                    mma16816(d2, Ah, Bh_);
                }
                ab += 1024u; b1 += 1024u; b2 += 1024u;
            }
        }

        // write gate partials (per K-half)
        if (doL1) {
            gpA_w[dr * GPLD + dc]           = d1[0];
            gpA_w[(dr + 1) * GPLD + dc]     = d1[1];
            gpA_w[dr * GPLD + dc + 8]       = d1[2];
            gpA_w[(dr + 1) * GPLD + dc + 8] = d1[3];
        }
        if (doL2) {
            gpB_w[dr * GPLD + dc]           = d2[0];
            gpB_w[(dr + 1) * GPLD + dc]     = d2[1];
            gpB_w[dr * GPLD + dc + 8]       = d2[2];
            gpB_w[(dr + 1) * GPLD + dc + 8] = d2[3];
        }
        __syncthreads();

        if (tid < 256) {
            // eltwise layer1
            if (doL1) {
                int p = g_pidx[i * 64 + bh * 32 + bl_e];
                float gv[4];
                #pragma unroll
                for (int gate = 0; gate < 4; ++gate) {
                    int r = (gate << 3) + uu;
                    gv[gate] = bs[r] + E2s[(p << 5) + r]
                             + gpA[r * GPLD + bl_e] + gpA[(32 + r) * GPLD + bl_e];
                }
                float ig = sig_ap(gv[0]);
                float fg = sig_ap(gv[1]);
                float gg = tanh_ap(gv[2]);
                float og = sig_ap(gv[3]);
                cst1 = fg * cst1 + ig * gg;
                float hv = og * tanh_ap(cst1);
                size_t off = (size_t)((i + 1) * 2 + bh) * HBH + eoff_h((ug << 3) + uu, bl_e);
                stg_h16(g_h1h + off, __float2half(hv));
            }
            // eltwise layer2
            if (doL2) {
                float gv[4];
                #pragma unroll
                for (int gate = 0; gate < 4; ++gate) {
                    int r = (gate << 3) + uu;
                    gv[gate] = bs[32 + r]
                             + gpB[r * GPLD + bl_e] + gpB[(32 + r) * GPLD + bl_e];
                }
                float ig = sig_ap(gv[0]);
                float fg = sig_ap(gv[1]);
                float gg = tanh_ap(gv[2]);
                float og = sig_ap(gv[3]);
                cst2 = fg * cst2 + ig * gg;
                float hv = og * tanh_ap(cst2);
                size_t off = (size_t)((i & 1) * 2 + bh) * HBH + eoff_h((ug << 3) + uu, bl_e);
                stg_h16(g_h2h + off, __float2half(hv));
            }
        }
        flag_barrier(++gen, bh, ug, tid);
    }

    // ======== head: LayerNorm + projection (final h2 at parity 0) ========
    if (cta < 8 && warp < 8) {
        int half = cta & 1;
        int bl = ((cta >> 1) << 3) + warp;
        const __half* h2h = g_h2h + (size_t)half * HBH;
        float s1 = 0.f, s2 = 0.f;
        for (int u = lane; u < H; u += 32) {
            float v = ldg_h16(h2h + eoff_h(u, bl));
            s1 += v; s2 += v * v;
        }
        #pragma unroll
        for (int o = 16; o; o >>= 1) {
            s1 += __shfl_xor_sync(0xFFFFFFFFu, s1, o);
            s2 += __shfl_xor_sync(0xFFFFFFFFu, s2, o);
        }
        float mu  = s1 * (1.f / H);
        float var = s2 * (1.f / H) - mu * mu;
        float rs  = rsqrtf(var + 1e-5f);
        float acc = 0.f;
        for (int u = lane; u < H; u += 32) {
            float v  = ldg_h16(h2h + eoff_h(u, bl));
            float hn = (v - mu) * rs * ln_g[u] + ln_b[u];
            acc += hn * Wp[u];
        }
        #pragma unroll
        for (int o = 16; o; o >>= 1) acc += __shfl_xor_sync(0xFFFFFFFFu, acc, o);
        if (lane == 0) out[half * 32 + bl] = acc + bp[0];
    }
}

// ---------------- launch ----------------
extern "C" void kernel_launch(void* const* d_in, const int* in_sizes, int n_in,
                              void* d_out, int out_size) {
    const void*  inp   = d_in[0];
    const float* embed = (const float*)d_in[1];
    const float* Wih   = (const float*)d_in[2];
    const float* Whh   = (const float*)d_in[3];
    const float* bih   = (const float*)d_in[4];
    const float* bhh   = (const float*)d_in[5];
    const float* ln_g  = (const float*)d_in[6];
    const float* ln_b  = (const float*)d_in[7];
    const float* Wp    = (const float*)d_in[8];
    const float* bp    = (const float*)d_in[9];
    float* out = (float*)d_out;

    detect_reset<<<1, 1>>>();
    detect_dtype<<<512, 256>>>((const unsigned*)inp);
    setup_misc<<<512, 256>>>(inp);
    setup_e2<<<128, 256>>>(embed, Wih);

    cudaFuncSetAttribute(lstm_persist, cudaFuncAttributeMaxDynamicSharedMemorySize, SMEM_TOT);
    lstm_persist<<<GRID, NTHREADS, SMEM_TOT>>>(Wih, Whh, bih, bhh, ln_g, ln_b, Wp, bp, out);
}